// round 15
// baseline (speedup 1.0000x reference)
#include <cuda_runtime.h>
#include <cuda_fp16.h>
#include <cstdint>

#define BATCH  8
#define CH     512
#define HW     4096
#define HEADS  4
#define DH     128
#define NG     32
#define EPS    1e-5f
#define NCHUNK 8

// ---------------- scratch (device globals; allocation-free) ----------------
__device__ __align__(1024) __half g_hnT[(size_t)BATCH * HW * CH];   // [b][n][c]
__device__ __align__(1024) __half g_qk [(size_t)BATCH * 1024 * HW]; // [b][o<1024][n] q,k
__device__ __align__(1024) __half g_vT [(size_t)BATCH * HW * CH];   // [b][n][e]
__device__ __align__(1024) __half g_at [(size_t)BATCH * HEADS * DH * DH]; // [bh][d][e]
__device__ __align__(1024) __half g_aoT[(size_t)BATCH * HW * CH];   // [b][n][c]
__device__ __align__(1024) __half g_w16[(size_t)4 * CH * CH];       // qkv_w then proj_w
__device__ __align__(1024) float  g_Sp [(size_t)BATCH * HEADS * NCHUNK * DH * DH]; // 16MB partials
__device__ float g_mean[BATCH * NG], g_rstd[BATCH * NG];

// ---------------- helpers ----------------
__device__ __forceinline__ uint32_t smem_u32(const void* p) {
    uint32_t a;
    asm("{ .reg .u64 t; cvta.to.shared.u64 t, %1; cvt.u32.u64 %0, t; }" : "=r"(a) : "l"(p));
    return a;
}
#define CPA16(sa, gp) \
    asm volatile("cp.async.cg.shared.global [%0], [%1], 16;" :: "r"(sa), "l"(gp))
#define CP_COMMIT() asm volatile("cp.async.commit_group;" ::: "memory")
#define CP_WAIT(n)  asm volatile("cp.async.wait_group %0;" :: "n"(n) : "memory")

// SMEM tile rows: 64 halves (128B) payload, padded row stride 144B (conflict-free).
#define RB 144

// 128 rows x 128B payload (one 64-K slab of a 128-row operand)
__device__ __forceinline__ void load_tile128(uint32_t sb, const __half* __restrict__ g,
                                             size_t stride, int tid) {
    #pragma unroll
    for (int i = 0; i < 4; i++) {
        int idx = tid + i * 256, row = idx >> 3, ch = idx & 7;
        CPA16(sb + row * RB + ch * 16, g + (size_t)row * stride + ch * 8);
    }
}

#define LDSM_X4(d0, d1, d2, d3, addr) \
    asm volatile("ldmatrix.sync.aligned.m8n8.x4.shared.b16 {%0,%1,%2,%3}, [%4];" \
        : "=r"(d0), "=r"(d1), "=r"(d2), "=r"(d3) : "r"(addr))

// Block GEMM: D[128 m][128 n] = A[128,K] x B[128,K], both K-major. 256 thr, 8 warps (2m x 4n),
// warp tile 64x32, fp32 accum acc[(mf*4+nf)*4+e]. 3-stage cp.async pipeline, 64-K slabs,
// one __syncthreads per slab, register double-buffered fragments. No trailing barrier.
__device__ __forceinline__ void hgemm_block(const __half* __restrict__ A, size_t sA,
                                            const __half* __restrict__ B, size_t sB,
                                            int K, char* sm, float* acc) {
    constexpr int ABYTES = 128 * RB;      // 18432
    constexpr int STAGE  = 2 * ABYTES;    // 36864
    uint32_t s0 = smem_u32(sm);
    int tid = threadIdx.x, lane = tid & 31, w = tid >> 5;
    int wm = w & 1, wn = w >> 1;

    uint32_t aoff = (uint32_t)((wm * 64 + (lane & 7) + ((lane >> 3) & 1) * 8) * RB
                               + (lane >> 4) * 16);
    uint32_t boff = (uint32_t)((wn * 32 + (lane >> 4) * 8 + (lane & 7)) * RB
                               + ((lane >> 3) & 1) * 16);

    #pragma unroll
    for (int i = 0; i < 64; i++) acc[i] = 0.f;

    const int S = K >> 6;                 // 64-K slabs
    load_tile128(s0, A, sA, tid);
    load_tile128(s0 + ABYTES, B, sB, tid);
    CP_COMMIT();
    if (S > 1) {
        load_tile128(s0 + STAGE, A + 64, sA, tid);
        load_tile128(s0 + STAGE + ABYTES, B + 64, sB, tid);
        CP_COMMIT();
    }

    uint32_t af[2][4][4], bf[2][4][2];
    int slot_c = 0, slot_p = 2;
    for (int s = 0; s < S; s++) {
        if (s + 1 < S) CP_WAIT(1); else CP_WAIT(0);
        __syncthreads();
        if (s + 2 < S) {
            load_tile128(s0 + slot_p * STAGE, A + (size_t)(s + 2) * 64, sA, tid);
            load_tile128(s0 + slot_p * STAGE + ABYTES, B + (size_t)(s + 2) * 64, sB, tid);
            CP_COMMIT();
        }
        uint32_t Ab = s0 + slot_c * STAGE + aoff;
        uint32_t Bb = s0 + slot_c * STAGE + ABYTES + boff;
        slot_c = (slot_c + 1 == 3) ? 0 : slot_c + 1;
        slot_p = (slot_p + 1 == 3) ? 0 : slot_p + 1;

        #pragma unroll
        for (int mf = 0; mf < 4; mf++)
            LDSM_X4(af[0][mf][0], af[0][mf][1], af[0][mf][2], af[0][mf][3],
                    Ab + mf * (16 * RB));
        #pragma unroll
        for (int p = 0; p < 2; p++)
            LDSM_X4(bf[0][2 * p][0], bf[0][2 * p][1], bf[0][2 * p + 1][0], bf[0][2 * p + 1][1],
                    Bb + p * (16 * RB));

        #pragma unroll
        for (int kk = 0; kk < 4; kk++) {
            const int cur = kk & 1, nxt = cur ^ 1;
            if (kk < 3) {
                #pragma unroll
                for (int mf = 0; mf < 4; mf++)
                    LDSM_X4(af[nxt][mf][0], af[nxt][mf][1], af[nxt][mf][2], af[nxt][mf][3],
                            Ab + mf * (16 * RB) + (kk + 1) * 32);
                #pragma unroll
                for (int p = 0; p < 2; p++)
                    LDSM_X4(bf[nxt][2 * p][0], bf[nxt][2 * p][1],
                            bf[nxt][2 * p + 1][0], bf[nxt][2 * p + 1][1],
                            Bb + p * (16 * RB) + (kk + 1) * 32);
            }
            #pragma unroll
            for (int mf = 0; mf < 4; mf++)
                #pragma unroll
                for (int nf = 0; nf < 4; nf++) {
                    float* c = acc + (mf * 4 + nf) * 4;
                    asm volatile(
                        "mma.sync.aligned.m16n8k16.row.col.f32.f16.f16.f32 "
                        "{%0,%1,%2,%3}, {%4,%5,%6,%7}, {%8,%9}, {%0,%1,%2,%3};"
                        : "+f"(c[0]), "+f"(c[1]), "+f"(c[2]), "+f"(c[3])
                        : "r"(af[cur][mf][0]), "r"(af[cur][mf][1]),
                          "r"(af[cur][mf][2]), "r"(af[cur][mf][3]),
                          "r"(bf[cur][nf][0]), "r"(bf[cur][nf][1]));
                }
        }
    }
}

// ---------------- GroupNorm ----------------
#define GSZ (CH / NG * HW)
__global__ __launch_bounds__(256) void gn_stats(const float* __restrict__ x) {
    int bg = blockIdx.x;
    const float4* p = (const float4*)(x + (size_t)bg * GSZ);
    float s = 0.f, sq = 0.f;
    for (int i = threadIdx.x; i < GSZ / 4; i += 256) {
        float4 v = p[i];
        s  += v.x + v.y + v.z + v.w;
        sq += v.x * v.x + v.y * v.y + v.z * v.z + v.w * v.w;
    }
    __shared__ float ss[8], sr[8];
    #pragma unroll
    for (int o = 16; o; o >>= 1) { s += __shfl_down_sync(~0u, s, o); sq += __shfl_down_sync(~0u, sq, o); }
    int w = threadIdx.x >> 5, l = threadIdx.x & 31;
    if (l == 0) { ss[w] = s; sr[w] = sq; }
    __syncthreads();
    if (w == 0) {
        s  = (l < 8) ? ss[l] : 0.f;
        sq = (l < 8) ? sr[l] : 0.f;
        #pragma unroll
        for (int o = 4; o; o >>= 1) { s += __shfl_down_sync(~0u, s, o); sq += __shfl_down_sync(~0u, sq, o); }
        if (l == 0) {
            float mu = s * (1.f / GSZ);
            float va = sq * (1.f / GSZ) - mu * mu;
            g_mean[bg] = mu;
            g_rstd[bg] = rsqrtf(va + EPS);
        }
    }
}

__global__ __launch_bounds__(256) void gn_apply_T(const float* __restrict__ x,
                                                  const float* __restrict__ gw,
                                                  const float* __restrict__ gb) {
    __shared__ float t[32][33];
    int b = blockIdx.z, c0 = blockIdx.y * 32, n0 = blockIdx.x * 32;
    int tx = threadIdx.x, ty = threadIdx.y;   // 32 x 8
    #pragma unroll
    for (int i = 0; i < 4; i++) {
        int c  = c0 + ty + i * 8;
        int bg = b * NG + (c >> 4);
        float r = g_rstd[bg];
        float w = gw[c] * r;
        float bb = gb[c] - g_mean[bg] * w;
        t[ty + i * 8][tx] = x[((size_t)b * CH + c) * HW + n0 + tx] * w + bb;
    }
    __syncthreads();
    #pragma unroll
    for (int i = 0; i < 4; i++) {
        int n = n0 + ty + i * 8;
        g_hnT[((size_t)b * HW + n) * CH + c0 + tx] = __float2half_rn(t[tx][ty + i * 8]);
    }
}

__global__ __launch_bounds__(256) void conv_w(const float* __restrict__ qw,
                                              const float* __restrict__ pw) {
    int i = blockIdx.x * 256 + threadIdx.x;
    const int NQ = 3 * CH * CH;
    float v = (i < NQ) ? qw[i] : pw[i - NQ];
    g_w16[i] = __float2half_rn(v);
}

// ---------------- QKV (q,k only): D[o][n] = qkv_w x hn, o0 < 1024 ----------------
__global__ __launch_bounds__(256, 2) void k_qkv(const float* __restrict__ qkv_b) {
    extern __shared__ char sm[];
    int n0 = blockIdx.x * 128, o0 = blockIdx.y * 128, b = blockIdx.z;
    float acc[64];
    hgemm_block(g_w16 + (size_t)o0 * CH, CH,
                g_hnT + ((size_t)b * HW + n0) * CH, CH, CH, sm, acc);

    int lane = threadIdx.x & 31, w = threadIdx.x >> 5;
    int wm = w & 1, wn = w >> 1, g = lane >> 2, ti = lane & 3;
    #pragma unroll
    for (int mf = 0; mf < 4; mf++) {
        int oa = o0 + wm * 64 + mf * 16 + g;
        float ba = qkv_b[oa], bb = qkv_b[oa + 8];
        #pragma unroll
        for (int nf = 0; nf < 4; nf++) {
            int n = n0 + wn * 32 + nf * 8 + ti * 2;
            float* c = acc + (mf * 4 + nf) * 4;
            *(__half2*)(g_qk + ((size_t)(b * 1024 + oa)) * HW + n) =
                __floats2half2_rn(c[0] + ba, c[1] + ba);
            *(__half2*)(g_qk + ((size_t)(b * 1024 + oa + 8)) * HW + n) =
                __floats2half2_rn(c[2] + bb, c[3] + bb);
        }
    }
}

// ---------------- fused: qk_part (blocks [0,256)) + v-projection (blocks [256,1280)) ----
// qk_part: Sp[bh][chunk] = q_chunk x k_chunk^T        (K = 512)
// v-part:  v[o][n] -> transpose -> vT[n][e]           (K = 512)
__global__ __launch_bounds__(256, 2) void k_fuse(const float* __restrict__ qkv_b) {
    extern __shared__ char sm[];
    int blk = blockIdx.x;
    int tid = threadIdx.x, lane = tid & 31, w = tid >> 5;
    int wm = w & 1, wn = w >> 1, g = lane >> 2, ti = lane & 3;
    float acc[64];

    if (blk < 256) {         // ---- qk_part ----
        int bh = blk & 31, chunk = blk >> 5, b = bh >> 2, h = bh & 3;
        const __half* A = g_qk + ((size_t)(b * 1024 + h * DH)) * HW + chunk * (HW / NCHUNK);
        const __half* B = g_qk + ((size_t)(b * 1024 + 512 + h * DH)) * HW + chunk * (HW / NCHUNK);
        hgemm_block(A, HW, B, HW, HW / NCHUNK, sm, acc);

        float* Sp = g_Sp + ((size_t)bh * NCHUNK + chunk) * DH * DH;
        #pragma unroll
        for (int mf = 0; mf < 4; mf++) {
            int ml = wm * 64 + mf * 16 + g;
            #pragma unroll
            for (int nf = 0; nf < 4; nf++) {
                int nl = wn * 32 + nf * 8 + ti * 2;
                float* c = acc + (mf * 4 + nf) * 4;
                *(float2*)(Sp + (size_t)ml * DH + nl)       = make_float2(c[0], c[1]);
                *(float2*)(Sp + (size_t)(ml + 8) * DH + nl) = make_float2(c[2], c[3]);
            }
        }
    } else {                 // ---- v-projection with transpose epilogue ----
        int idx = blk - 256;
        int n0 = (idx & 31) * 128, o0 = 1024 + ((idx >> 5) & 3) * 128, b = idx >> 7;
        hgemm_block(g_w16 + (size_t)o0 * CH, CH,
                    g_hnT + ((size_t)b * HW + n0) * CH, CH, CH, sm, acc);
        __syncthreads();
        __half* Ts = (__half*)sm;   // [128 n][136]
        #pragma unroll
        for (int mf = 0; mf < 4; mf++) {
            int ol = wm * 64 + mf * 16 + g;
            float ba = qkv_b[o0 + ol], bb = qkv_b[o0 + ol + 8];
            #pragma unroll
            for (int nf = 0; nf < 4; nf++) {
                int nl = wn * 32 + nf * 8 + ti * 2;
                float* c = acc + (mf * 4 + nf) * 4;
                Ts[(nl    ) * 136 + ol    ] = __float2half_rn(c[0] + ba);
                Ts[(nl + 1) * 136 + ol    ] = __float2half_rn(c[1] + ba);
                Ts[(nl    ) * 136 + ol + 8] = __float2half_rn(c[2] + bb);
                Ts[(nl + 1) * 136 + ol + 8] = __float2half_rn(c[3] + bb);
            }
        }
        __syncthreads();
        int r = tid >> 1, part = tid & 1;
        uint4* dst = (uint4*)(g_vT + ((size_t)b * HW + n0 + r) * CH + (o0 - 1024) + part * 64);
        const uint4* src = (const uint4*)(Ts + r * 136 + part * 64);
        #pragma unroll
        for (int j = 0; j < 8; j++) dst[j] = src[j];
    }
}

// ---------------- reduce partials + scale + softmax -> g_at fp16 ----------------
__global__ __launch_bounds__(128) void k_softmax() {
    int row = blockIdx.x, bh = blockIdx.y, t = threadIdx.x;
    const float* Sp = g_Sp + (size_t)bh * NCHUNK * DH * DH + (size_t)row * DH + t;
    float v = 0.f;
    #pragma unroll
    for (int c = 0; c < NCHUNK; c++) v += Sp[(size_t)c * DH * DH];
    v *= 0.08838834764831845f;   // 128^-0.5

    __shared__ float red[4];
    int w = t >> 5, l = t & 31;
    float m = v;
    #pragma unroll
    for (int o = 16; o; o >>= 1) m = fmaxf(m, __shfl_xor_sync(~0u, m, o));
    if (l == 0) red[w] = m;
    __syncthreads();
    m = fmaxf(fmaxf(red[0], red[1]), fmaxf(red[2], red[3]));
    __syncthreads();
    float e = __expf(v - m), su = e;
    #pragma unroll
    for (int o = 16; o; o >>= 1) su += __shfl_xor_sync(~0u, su, o);
    if (l == 0) red[w] = su;
    __syncthreads();
    su = red[0] + red[1] + red[2] + red[3];
    g_at[((size_t)bh * DH + row) * DH + t] = __float2half_rn(e / su);
}

// ---------------- AV: ao[d][n] -> aoT[n][c] ----------------
__global__ __launch_bounds__(256, 2) void k_av() {
    extern __shared__ char sm[];
    int n0 = blockIdx.x * 128, bh = blockIdx.z, b = bh >> 2, h = bh & 3;
    float acc[64];
    hgemm_block(g_at + (size_t)bh * DH * DH, DH,
                g_vT + ((size_t)b * HW + n0) * CH + h * DH, CH, DH, sm, acc);
    __syncthreads();

    __half* Ts = (__half*)sm;   // [128 n][136]
    int tid = threadIdx.x, lane = tid & 31, w = tid >> 5;
    int wm = w & 1, wn = w >> 1, g = lane >> 2, ti = lane & 3;
    #pragma unroll
    for (int mf = 0; mf < 4; mf++) {
        int dl = wm * 64 + mf * 16 + g;
        #pragma unroll
        for (int nf = 0; nf < 4; nf++) {
            int nl = wn * 32 + nf * 8 + ti * 2;
            float* c = acc + (mf * 4 + nf) * 4;
            Ts[(nl    ) * 136 + dl    ] = __float2half_rn(c[0]);
            Ts[(nl + 1) * 136 + dl    ] = __float2half_rn(c[1]);
            Ts[(nl    ) * 136 + dl + 8] = __float2half_rn(c[2]);
            Ts[(nl + 1) * 136 + dl + 8] = __float2half_rn(c[3]);
        }
    }
    __syncthreads();
    int r = tid >> 1, part = tid & 1;
    uint4* dst = (uint4*)(g_aoT + ((size_t)b * HW + n0 + r) * CH + h * DH + part * 64);
    const uint4* src = (const uint4*)(Ts + r * 136 + part * 64);
    #pragma unroll
    for (int j = 0; j < 8; j++) dst[j] = src[j];
}

// ---------------- proj + bias + residual ----------------
__global__ __launch_bounds__(256, 2) void k_proj(const float* __restrict__ proj_b,
                                                 const float* __restrict__ x,
                                                 float* __restrict__ out) {
    extern __shared__ char sm[];
    int n0 = blockIdx.x * 128, o0 = blockIdx.y * 128, b = blockIdx.z;
    float acc[64];
    hgemm_block(g_w16 + (size_t)3 * CH * CH + (size_t)o0 * CH, CH,
                g_aoT + ((size_t)b * HW + n0) * CH, CH, CH, sm, acc);

    int tid = threadIdx.x, lane = tid & 31, w = tid >> 5;
    int wm = w & 1, wn = w >> 1, g = lane >> 2, ti = lane & 3;
    #pragma unroll
    for (int mf = 0; mf < 4; mf++) {
        int oa = o0 + wm * 64 + mf * 16 + g;
        float ba = proj_b[oa], bb = proj_b[oa + 8];
        #pragma unroll
        for (int nf = 0; nf < 4; nf++) {
            int n = n0 + wn * 32 + nf * 8 + ti * 2;
            float* c = acc + (mf * 4 + nf) * 4;
            size_t o1 = ((size_t)b * CH + oa) * HW + n;
            size_t o2 = ((size_t)b * CH + oa + 8) * HW + n;
            float2 r1 = *(const float2*)(x + o1);
            float2 r2 = *(const float2*)(x + o2);
            *(float2*)(out + o1) = make_float2(c[0] + ba + r1.x, c[1] + ba + r1.y);
            *(float2*)(out + o2) = make_float2(c[2] + bb + r2.x, c[3] + bb + r2.y);
        }
    }
}

// ---------------- host ----------------
#define SMEM_G (2 * 128 * RB * 3)   // 110592/CTA; x2 CTAs = 216KB/SM

extern "C" void kernel_launch(void* const* d_in, const int* in_sizes, int n_in,
                              void* d_out, int out_size) {
    const float* x      = (const float*)d_in[0];
    const float* gn_w   = (const float*)d_in[1];
    const float* gn_b   = (const float*)d_in[2];
    const float* qkv_w  = (const float*)d_in[3];
    const float* qkv_b  = (const float*)d_in[4];
    const float* proj_w = (const float*)d_in[5];
    const float* proj_b = (const float*)d_in[6];
    float* out = (float*)d_out;

    cudaFuncSetAttribute(k_qkv,  cudaFuncAttributeMaxDynamicSharedMemorySize, SMEM_G);
    cudaFuncSetAttribute(k_fuse, cudaFuncAttributeMaxDynamicSharedMemorySize, SMEM_G);
    cudaFuncSetAttribute(k_av,   cudaFuncAttributeMaxDynamicSharedMemorySize, SMEM_G);
    cudaFuncSetAttribute(k_proj, cudaFuncAttributeMaxDynamicSharedMemorySize, SMEM_G);

    gn_stats<<<BATCH * NG, 256>>>(x);
    gn_apply_T<<<dim3(HW / 32, CH / 32, BATCH), dim3(32, 8)>>>(x, gn_w, gn_b);
    conv_w<<<(4 * CH * CH) / 256, 256>>>(qkv_w, proj_w);

    k_qkv <<<dim3(HW / 128, 8, BATCH), 256, SMEM_G>>>(qkv_b);     // q,k only
    k_fuse<<<1280, 256, SMEM_G>>>(qkv_b);                          // qk_part + v-projection
    k_softmax<<<dim3(DH, BATCH * HEADS), 128>>>();
    k_av  <<<dim3(HW / 128, 1, BATCH * HEADS), 256, SMEM_G>>>();
    k_proj<<<dim3(HW / 128, CH / 128, BATCH), 256, SMEM_G>>>(proj_b, x, out);

    (void)in_sizes; (void)n_in; (void)out_size;
}